// round 5
// baseline (speedup 1.0000x reference)
#include <cuda_runtime.h>

#define NN    192
#define GRID  128
#define NG    4                      // groups of 192 threads per block
#define NT    (NN * NG)              // 768 threads
#define VB    (GRID * NG)            // 512 virtual workers
#define SROW  196                    // padded smem row stride (floats)
#define SGS_F (NN * SROW)            // 37632
#define XS_F  (NG * 2 * NN)          // 1536
#define HS_F  (NG * 192)             // 768
#define SMEM_BYTES ((SGS_F + XS_F + HS_F) * 4)   // 159,744 B

// ---- device-global scratch ----
__device__ float g_X1[98304];
__device__ float g_G1[98304];
__device__ float g_P1[49152];
__device__ float g_P2[49152];
__device__ float g_P3[49152];

// ---- replay-safe grid barrier ----
__device__ unsigned g_cnt = 0;
__device__ volatile unsigned g_gen = 0;

__device__ __forceinline__ void gsync() {
    __syncthreads();
    if (threadIdx.x == 0) {
        __threadfence();
        unsigned gen0 = g_gen;
        if (atomicAdd(&g_cnt, 1u) == GRID - 1) {
            g_cnt = 0;
            __threadfence();
            g_gen = gen0 + 1;
        } else {
            while (g_gen == gen0) __nanosleep(32);
        }
        __threadfence();
    }
    __syncthreads();
}

// x0 accessor: 0 = raw X (N,T); 1 = buffer [(t*C+c)*NN+n]; 5 = up2+relu half-T
template <int X0M>
__device__ __forceinline__ float x0get(const float* __restrict__ P,
                                       int t, int c, int n, int C) {
    if (X0M == 0) return P[n * 32 + t];
    if (X0M == 1) return P[(t * C + c) * NN + n];
    if (t & 1) return 0.0f;
    float v = P[((t >> 1) * C + c) * NN + n];
    return v > 0.0f ? v : 0.0f;
}

// dot(sg_row[n], xv[0..191]); xv is a group-local smem vector (broadcast reads)
__device__ __forceinline__ float mv1(const float* __restrict__ sgs,
                                     const float* __restrict__ xv, int n) {
    const float4* __restrict__ srow = (const float4*)(sgs + n * SROW);
    const float4* __restrict__ xr   = (const float4*)xv;
    float a0 = 0.f, a1 = 0.f, a2 = 0.f, a3 = 0.f;
#pragma unroll 4
    for (int q = 0; q < NN / 4; q++) {
        const float4 s = srow[q];
        const float4 x = xr[q];
        a0 = fmaf(s.x, x.x, a0);
        a1 = fmaf(s.y, x.y, a1);
        a2 = fmaf(s.z, x.z, a2);
        a3 = fmaf(s.w, x.w, a3);
    }
    return (a0 + a1) + (a2 + a3);
}

// ---------------------------------------------------------------------------
// Encoder AB (1 pair per vgroup): g0(t), g0(t-1), x1 = s.(x0,g0), g1 = Sg@x1
// ---------------------------------------------------------------------------
template <int X0M>
__device__ void ab_enc(const float* __restrict__ P, const float* __restrict__ sgs,
                       float* xa, float* xb,
                       float s00, float s01, float s10, float s11,
                       int C, int T, int npairs, int n, int vb) {
    const bool act = vb < npairs;
    const int pc = act ? vb : npairs - 1;
    const int t = pc / C, c = pc % C, tm = (t + T - 1) % T;

    xa[n] = x0get<X0M>(P, t,  c, n, C);
    xb[n] = x0get<X0M>(P, tm, c, n, C);
    __syncthreads();

    const float g0t = mv1(sgs, xa, n);
    const float g0m = mv1(sgs, xb, n);
    const float x1  = s00 * xa[n] + s01 * g0t + s10 * xb[n] + s11 * g0m;
    if (act) g_X1[pc * NN + n] = x1;
    __syncthreads();
    xa[n] = x1;
    __syncthreads();

    const float g1 = mv1(sgs, xa, n);
    if (act) g_G1[pc * NN + n] = g1;
    __syncthreads();
}

// ---------------------------------------------------------------------------
// Decoder AB: x0 = zero-stuff up2(+relu); g0 odd-t is zero -> 1 matvec.
//   u = t>>1;  t even: x1 = s00*x0u + s01*g0u ; t odd: x1 = s10*x0u + s11*g0u
// ---------------------------------------------------------------------------
__device__ void ab_dec(const float* __restrict__ P, const float* __restrict__ sgs,
                       float* xa,
                       float s00, float s01, float s10, float s11,
                       int C, int npairs, int n, int vb) {
    const bool act = vb < npairs;
    const int pc = act ? vb : npairs - 1;
    const int t = pc / C, c = pc % C, u = t >> 1;

    float v = P[(u * C + c) * NN + n];
    xa[n] = v > 0.0f ? v : 0.0f;
    __syncthreads();

    const float g0 = mv1(sgs, xa, n);
    const float ca = (t & 1) ? s10 : s00;
    const float cb = (t & 1) ? s11 : s01;
    const float x1 = ca * xa[n] + cb * g0;
    if (act) g_X1[pc * NN + n] = x1;
    __syncthreads();
    xa[n] = x1;
    __syncthreads();

    const float g1 = mv1(sgs, xa, n);
    if (act) g_G1[pc * NN + n] = g1;
    __syncthreads();
}

// ---------------------------------------------------------------------------
// Projection (1 item per vgroup): y = sum_c x0*h0 + x1*h1 + x2*h2,
// x2 = s00*x1(t)+s01*g1(t)+s10*x1(tm)+s11*g1(tm).
// EMODE 0: pool time pair + relu; 1: plain; 2: COUT==1 transpose write.
// ---------------------------------------------------------------------------
template <int CIN, int COUT, int OG, int EMODE, int X0M>
__device__ void proj(const float* __restrict__ P, const float* __restrict__ h,
                     float s00, float s01, float s10, float s11,
                     float* __restrict__ outp, int T, float* hsg, int n, int vb) {
    const int ogroups = COUT / OG;
    const int items = (EMODE == 0 ? T / 2 : T) * ogroups;
    const bool act = vb < items;
    const int it = act ? vb : items - 1;
    const int og = it % ogroups, ti = it / ogroups, o0 = og * OG;

    for (int idx = n; idx < OG * CIN * 3; idx += NN)
        hsg[idx] = h[o0 * CIN * 3 + idx];
    __syncthreads();

    const int nt = (EMODE == 0) ? 2 : 1;
    const int tb = (EMODE == 0) ? ti * 2 : ti;

    float best[OG];
#pragma unroll
    for (int o = 0; o < OG; o++) best[o] = -3.0e38f;

    for (int q = 0; q < nt; q++) {
        const int t = tb + q, tm = (t + T - 1) % T;
        float y[OG];
#pragma unroll
        for (int o = 0; o < OG; o++) y[o] = 0.0f;

#pragma unroll 4
        for (int c = 0; c < CIN; c++) {
            const float v0  = x0get<X0M>(P, t, c, n, CIN);
            const float v1  = g_X1[(t  * CIN + c) * NN + n];
            const float g1t = g_G1[(t  * CIN + c) * NN + n];
            const float v1m = g_X1[(tm * CIN + c) * NN + n];
            const float g1m = g_G1[(tm * CIN + c) * NN + n];
            const float v2  = s00 * v1 + s01 * g1t + s10 * v1m + s11 * g1m;
#pragma unroll
            for (int o = 0; o < OG; o++) {
                const float* hp = &hsg[(o * CIN + c) * 3];
                y[o] = fmaf(v0, hp[0], y[o]);
                y[o] = fmaf(v1, hp[1], y[o]);
                y[o] = fmaf(v2, hp[2], y[o]);
            }
        }

        if (EMODE == 0) {
#pragma unroll
            for (int o = 0; o < OG; o++) best[o] = fmaxf(best[o], y[o]);
        } else if (EMODE == 1) {
            if (act)
#pragma unroll
                for (int o = 0; o < OG; o++)
                    outp[(t * COUT + o0 + o) * NN + n] = y[o];
        } else {
            if (act) outp[n * T + t] = y[0];
        }
    }
    if (EMODE == 0 && act) {
#pragma unroll
        for (int o = 0; o < OG; o++)
            outp[(ti * COUT + o0 + o) * NN + n] = fmaxf(best[o], 0.0f);
    }
    __syncthreads();
}

// ---------------------------------------------------------------------------
// Single fused kernel: 768 threads = 4 groups x 192; smem-resident Sg.
// ---------------------------------------------------------------------------
extern __shared__ float sm[];
__global__ void __launch_bounds__(NT, 1)
fused(const float* __restrict__ X,  const float* __restrict__ Sg,
      const float* __restrict__ s4,
      const float* __restrict__ he1, const float* __restrict__ he2,
      const float* __restrict__ hd1, const float* __restrict__ hd2,
      float* __restrict__ out) {
    const int tid = threadIdx.x;
    const int g   = tid / NN;        // group 0..3
    const int n   = tid % NN;        // node
    const int vb  = blockIdx.x * NG + g;

    float* sgs = sm;                          // [NN][SROW]
    float* xa  = sm + SGS_F + g * 2 * NN;     // group vec A
    float* xb  = xa + NN;                     // group vec B
    float* hsg = sm + SGS_F + XS_F + g * 192; // group filter tile

    // Fill Sg into padded smem: 12 x LDG.128 per thread, coalesced.
    {
        const float4* __restrict__ src = (const float4*)Sg;
#pragma unroll
        for (int i = tid; i < NN * (NN / 4); i += NT) {
            const int row = i / (NN / 4), qq = i % (NN / 4);
            ((float4*)(sgs + row * SROW))[qq] = src[row * (NN / 4) + qq];
        }
    }
    __syncthreads();

    const float s00 = s4[0], s01 = s4[1], s10 = s4[2], s11 = s4[3];

    // ---- Encoder layer 1: T=32, C=1 -> 16, pool ----
    ab_enc<0>(X, sgs, xa, xb, s00, s01, s10, s11, 1, 32, 32, n, vb);
    gsync();
    proj<1, 16, 2, 0, 0>(X, he1, s00, s01, s10, s11, g_P1, 32, hsg, n, vb);
    gsync();

    // ---- Encoder layer 2: T=16, C=16 -> 32, pool ----
    ab_enc<1>(g_P1, sgs, xa, xb, s00, s01, s10, s11, 16, 16, 256, n, vb);
    gsync();
    proj<16, 32, 2, 0, 1>(g_P1, he2, s00, s01, s10, s11, g_P2, 16, hsg, n, vb);
    gsync();

    // ---- Decoder layer 1: up 8->16 (+relu), C=32 -> 16, plain ----
    ab_dec(g_P2, sgs, xa, s00, s01, s10, s11, 32, 512, n, vb);
    gsync();
    proj<32, 16, 2, 1, 5>(g_P2, hd1, s00, s01, s10, s11, g_P3, 16, hsg, n, vb);
    gsync();

    // ---- Decoder layer 2: up 16->32 (+relu), C=16 -> 1, transpose out ----
    ab_dec(g_P3, sgs, xa, s00, s01, s10, s11, 16, 512, n, vb);
    gsync();
    proj<16, 1, 1, 2, 5>(g_P3, hd2, s00, s01, s10, s11, out, 32, hsg, n, vb);
}

extern "C" void kernel_launch(void* const* d_in, const int* in_sizes, int n_in,
                              void* d_out, int out_size) {
    const float* X   = (const float*)d_in[0];  // (192, 32)
    const float* Sg  = (const float*)d_in[1];  // (192, 192)
    const float* s   = (const float*)d_in[2];  // (2, 2)
    const float* he1 = (const float*)d_in[3];  // (16, 1, 3)
    const float* he2 = (const float*)d_in[4];  // (32, 16, 3)
    const float* hd1 = (const float*)d_in[5];  // (16, 32, 3)
    const float* hd2 = (const float*)d_in[6];  // (1, 16, 3)
    float* out = (float*)d_out;                // (192, 32)

    cudaFuncSetAttribute(fused, cudaFuncAttributeMaxDynamicSharedMemorySize,
                         SMEM_BYTES);
    fused<<<GRID, NT, SMEM_BYTES>>>(X, Sg, s, he1, he2, hd1, hd2, out);
}

// round 6
// speedup vs baseline: 1.3952x; 1.3952x over previous
#include <cuda_runtime.h>

#define NN    192
#define GRID  128
#define NG    4                      // m-slices / reduce groups
#define NT    (NN * NG)              // 768 threads
#define MS    (NN / NG)              // 48 m per slice
#define SROW  196                    // padded smem row stride (floats)
#define SGS_F (NN * SROW)            // 37632
#define XS_F  (8 * NN)               // 1536
#define PT_F  (8 * NG * NN)          // 6144 partials
#define HS_F  (NG * 192)             // 768
#define SMEM_BYTES ((SGS_F + XS_F + PT_F + HS_F) * 4)   // 184,320 B

// ---- device-global scratch ----
__device__ float g_XG[196608];  // interleaved {x1, g1} per (pair, n)
__device__ float g_P1[49152];   // enc1 out (pooled+relu)  [(t*16+o)*NN+n]
__device__ float g_P2[49152];   // enc2 out (pooled+relu)  [(t*32+o)*NN+n]
__device__ float g_P3[49152];   // dec1 out (plain)        [(t*16+o)*NN+n]

// ---- replay-safe grid barrier ----
__device__ unsigned g_cnt = 0;
__device__ volatile unsigned g_gen = 0;

__device__ __forceinline__ void gsync() {
    __syncthreads();
    if (threadIdx.x == 0) {
        __threadfence();
        unsigned gen0 = g_gen;
        if (atomicAdd(&g_cnt, 1u) == GRID - 1) {
            g_cnt = 0;
            __threadfence();
            g_gen = gen0 + 1;
        } else {
            while (g_gen == gen0) __nanosleep(32);
        }
        __threadfence();
    }
    __syncthreads();
}

// x0 accessor: 0 = raw X (N,T); 1 = buffer [(t*C+c)*NN+n]; 5 = up2+relu half-T
template <int X0M>
__device__ __forceinline__ float x0get(const float* __restrict__ P,
                                       int t, int c, int n, int C) {
    if (X0M == 0) return P[n * 32 + t];
    if (X0M == 1) return P[(t * C + c) * NN + n];
    if (t & 1) return 0.0f;
    float v = P[((t >> 1) * C + c) * NN + n];
    return v > 0.0f ? v : 0.0f;
}

// Partial matvec: thread (n,g) accumulates Sg[n][m-slice g] against V staged
// vectors; partials -> part[(v*4+g)*NN + n].
template <int V>
__device__ __forceinline__ void mvpart(const float* __restrict__ sgs,
                                       const float* __restrict__ xs,
                                       float* __restrict__ part, int n, int g) {
    float acc[V];
#pragma unroll
    for (int v = 0; v < V; v++) acc[v] = 0.0f;
    const float4* __restrict__ srow = (const float4*)(sgs + n * SROW + g * MS);
#pragma unroll
    for (int q = 0; q < MS / 4; q++) {
        const float4 sg = srow[q];
#pragma unroll
        for (int v = 0; v < V; v++) {
            const float4 xv = ((const float4*)(xs + v * NN + g * MS))[q];
            acc[v] = fmaf(sg.x, xv.x, acc[v]);
            acc[v] = fmaf(sg.y, xv.y, acc[v]);
            acc[v] = fmaf(sg.z, xv.z, acc[v]);
            acc[v] = fmaf(sg.w, xv.w, acc[v]);
        }
    }
#pragma unroll
    for (int v = 0; v < V; v++) part[(v * 4 + g) * NN + n] = acc[v];
}

__device__ __forceinline__ float rsum(const float* __restrict__ part,
                                      int v, int n) {
    return (part[(v * 4 + 0) * NN + n] + part[(v * 4 + 1) * NN + n])
         + (part[(v * 4 + 2) * NN + n] + part[(v * 4 + 3) * NN + n]);
}

// ---------------------------------------------------------------------------
// Encoder AB: block handles 4 pairs. Pass1: g0(t_j), g0(t_j-1) (8 vectors);
// x1_j = s.(x0,g0); Pass2: g1_j = Sg@x1_j. Writes {x1,g1} -> g_XG.
// ---------------------------------------------------------------------------
template <int X0M>
__device__ void ab_enc(const float* __restrict__ P, const float* __restrict__ sgs,
                       float* xs, float* part,
                       float s00, float s01, float s10, float s11,
                       int C, int T, int n, int g, int b) {
    const int p0 = b * 4;

    // stage 8 vectors: v<4 -> x0(t_v), v>=4 -> x0(t_{v-4} - 1)
#pragma unroll
    for (int v = g; v < 8; v += NG) {
        const int j = v & 3;
        const int pc = p0 + j;
        int t = pc / C;
        const int c = pc % C;
        if (v >= 4) t = (t + T - 1) % T;
        xs[v * NN + n] = x0get<X0M>(P, t, c, n, C);
    }
    __syncthreads();

    mvpart<8>(sgs, xs, part, n, g);
    __syncthreads();

    // reduce + build x1 (thread (n,g) owns pair j=g)
    {
        const int j = g;
        const float g0t = rsum(part, j, n);
        const float g0m = rsum(part, 4 + j, n);
        const float x1 = s00 * xs[j * NN + n] + s01 * g0t
                       + s10 * xs[(4 + j) * NN + n] + s11 * g0m;
        xs[j * NN + n] = x1;   // sole reader/writer of this element this phase
    }
    __syncthreads();

    mvpart<4>(sgs, xs, part, n, g);
    __syncthreads();

    {
        const int j = g;
        const float g1 = rsum(part, j, n);
        ((float2*)g_XG)[(p0 + j) * NN + n] = make_float2(xs[j * NN + n], g1);
    }
}

// ---------------------------------------------------------------------------
// Decoder AB: x0 = zero-stuff up2(+relu); g0 at odd t is zero -> 1 g0 matvec.
//   u = t>>1; t even: x1 = s00*x0u + s01*g0u ; t odd: x1 = s10*x0u + s11*g0u
// ---------------------------------------------------------------------------
__device__ void ab_dec(const float* __restrict__ P, const float* __restrict__ sgs,
                       float* xs, float* part,
                       float s00, float s01, float s10, float s11,
                       int C, int n, int g, int b) {
    const int p0 = b * 4;

    {   // stage 4 vectors, one per group-owned pair
        const int j = g;
        const int pc = p0 + j;
        const int t = pc / C, c = pc % C, u = t >> 1;
        const float v = P[(u * C + c) * NN + n];
        xs[j * NN + n] = v > 0.0f ? v : 0.0f;
    }
    __syncthreads();

    mvpart<4>(sgs, xs, part, n, g);
    __syncthreads();

    {
        const int j = g;
        const int t = (p0 + j) / C;
        const float g0 = rsum(part, j, n);
        const float ca = (t & 1) ? s10 : s00;
        const float cb = (t & 1) ? s11 : s01;
        xs[j * NN + n] = ca * xs[j * NN + n] + cb * g0;
    }
    __syncthreads();

    mvpart<4>(sgs, xs, part, n, g);
    __syncthreads();

    {
        const int j = g;
        const float g1 = rsum(part, j, n);
        ((float2*)g_XG)[(p0 + j) * NN + n] = make_float2(xs[j * NN + n], g1);
    }
}

// ---------------------------------------------------------------------------
// Projection (1 item per vgroup): y = sum_c x0*h0 + x1*h1 + x2*h2,
// x2 = s00*x1(t)+s01*g1(t)+s10*x1(tm)+s11*g1(tm); {x1,g1} as float2 loads.
// EMODE 0: pool time pair + relu; 1: plain; 2: COUT==1 transpose write.
// ---------------------------------------------------------------------------
template <int CIN, int COUT, int OG, int EMODE, int X0M>
__device__ void proj(const float* __restrict__ P, const float* __restrict__ h,
                     float s00, float s01, float s10, float s11,
                     float* __restrict__ outp, int T, float* hsg, int n, int vb) {
    const int ogroups = COUT / OG;
    const int items = (EMODE == 0 ? T / 2 : T) * ogroups;
    const bool act = vb < items;
    const int it = act ? vb : items - 1;
    const int og = it % ogroups, ti = it / ogroups, o0 = og * OG;

    for (int idx = n; idx < OG * CIN * 3; idx += NN)
        hsg[idx] = h[o0 * CIN * 3 + idx];
    __syncthreads();

    const int nt = (EMODE == 0) ? 2 : 1;
    const int tb = (EMODE == 0) ? ti * 2 : ti;
    const float2* __restrict__ XG = (const float2*)g_XG;

    float best[OG];
#pragma unroll
    for (int o = 0; o < OG; o++) best[o] = -3.0e38f;

    for (int q = 0; q < nt; q++) {
        const int t = tb + q, tm = (t + T - 1) % T;
        float y[OG];
#pragma unroll
        for (int o = 0; o < OG; o++) y[o] = 0.0f;

#pragma unroll 4
        for (int c = 0; c < CIN; c++) {
            const float v0 = x0get<X0M>(P, t, c, n, CIN);
            const float2 xgt = XG[(t  * CIN + c) * NN + n];
            const float2 xgm = XG[(tm * CIN + c) * NN + n];
            const float v2 = s00 * xgt.x + s01 * xgt.y
                           + s10 * xgm.x + s11 * xgm.y;
#pragma unroll
            for (int o = 0; o < OG; o++) {
                const float* hp = &hsg[(o * CIN + c) * 3];
                y[o] = fmaf(v0,    hp[0], y[o]);
                y[o] = fmaf(xgt.x, hp[1], y[o]);
                y[o] = fmaf(v2,    hp[2], y[o]);
            }
        }

        if (EMODE == 0) {
#pragma unroll
            for (int o = 0; o < OG; o++) best[o] = fmaxf(best[o], y[o]);
        } else if (EMODE == 1) {
            if (act)
#pragma unroll
                for (int o = 0; o < OG; o++)
                    outp[(t * COUT + o0 + o) * NN + n] = y[o];
        } else {
            if (act) outp[n * T + t] = y[0];
        }
    }
    if (EMODE == 0 && act) {
#pragma unroll
        for (int o = 0; o < OG; o++)
            outp[(ti * COUT + o0 + o) * NN + n] = fmaxf(best[o], 0.0f);
    }
    __syncthreads();
}

// ---------------------------------------------------------------------------
// Single fused kernel: 768 thr = 192 n x 4 m-slices; smem-resident Sg;
// J=4 pairs per block in AB stages; 7 grid barriers.
// ---------------------------------------------------------------------------
extern __shared__ float sm[];
__global__ void __launch_bounds__(NT, 1)
fused(const float* __restrict__ X,  const float* __restrict__ Sg,
      const float* __restrict__ s4,
      const float* __restrict__ he1, const float* __restrict__ he2,
      const float* __restrict__ hd1, const float* __restrict__ hd2,
      float* __restrict__ out) {
    const int tid = threadIdx.x;
    const int g   = tid / NN;        // m-slice / pair-owner group (warps uniform)
    const int n   = tid % NN;
    const int b   = blockIdx.x;
    const int vb  = b * NG + g;      // 512 virtual groups for proj

    float* sgs  = sm;                           // [NN][SROW]
    float* xs   = sm + SGS_F;                   // 8 staged vectors
    float* part = xs + XS_F;                    // [8][4][NN] partials
    float* hsg  = part + PT_F + g * 192;        // per-group filter tile

    // Fill Sg into padded smem: float4 coalesced.
    {
        const float4* __restrict__ src = (const float4*)Sg;
#pragma unroll
        for (int i = tid; i < NN * (NN / 4); i += NT) {
            const int row = i / (NN / 4), qq = i % (NN / 4);
            ((float4*)(sgs + row * SROW))[qq] = src[row * (NN / 4) + qq];
        }
    }
    __syncthreads();

    const float s00 = s4[0], s01 = s4[1], s10 = s4[2], s11 = s4[3];

    // ---- Encoder layer 1: T=32, C=1 -> 16, pool (32 pairs: blocks 0..7) ----
    if (b * 4 < 32)
        ab_enc<0>(X, sgs, xs, part, s00, s01, s10, s11, 1, 32, n, g, b);
    gsync();
    proj<1, 16, 2, 0, 0>(X, he1, s00, s01, s10, s11, g_P1, 32, hsg, n, vb);
    gsync();

    // ---- Encoder layer 2: T=16, C=16 -> 32, pool (256 pairs: blocks 0..63) ----
    if (b * 4 < 256)
        ab_enc<1>(g_P1, sgs, xs, part, s00, s01, s10, s11, 16, 16, n, g, b);
    gsync();
    proj<16, 32, 2, 0, 1>(g_P1, he2, s00, s01, s10, s11, g_P2, 16, hsg, n, vb);
    gsync();

    // ---- Decoder layer 1: up 8->16 (+relu), C=32 -> 16, plain (512 pairs) ----
    ab_dec(g_P2, sgs, xs, part, s00, s01, s10, s11, 32, n, g, b);
    gsync();
    proj<32, 16, 2, 1, 5>(g_P2, hd1, s00, s01, s10, s11, g_P3, 16, hsg, n, vb);
    gsync();

    // ---- Decoder layer 2: up 16->32 (+relu), C=16 -> 1, transpose (512 pairs) ----
    ab_dec(g_P3, sgs, xs, part, s00, s01, s10, s11, 16, n, g, b);
    gsync();
    proj<16, 1, 1, 2, 5>(g_P3, hd2, s00, s01, s10, s11, out, 32, hsg, n, vb);
}

extern "C" void kernel_launch(void* const* d_in, const int* in_sizes, int n_in,
                              void* d_out, int out_size) {
    const float* X   = (const float*)d_in[0];  // (192, 32)
    const float* Sg  = (const float*)d_in[1];  // (192, 192)
    const float* s   = (const float*)d_in[2];  // (2, 2)
    const float* he1 = (const float*)d_in[3];  // (16, 1, 3)
    const float* he2 = (const float*)d_in[4];  // (32, 16, 3)
    const float* hd1 = (const float*)d_in[5];  // (16, 32, 3)
    const float* hd2 = (const float*)d_in[6];  // (1, 16, 3)
    float* out = (float*)d_out;                // (192, 32)

    cudaFuncSetAttribute(fused, cudaFuncAttributeMaxDynamicSharedMemorySize,
                         SMEM_BYTES);
    fused<<<GRID, NT, SMEM_BYTES>>>(X, Sg, s, he1, he2, hd1, hd2, out);
}

// round 7
// speedup vs baseline: 1.5937x; 1.1423x over previous
#include <cuda_runtime.h>

#define NN    192
#define GRID  128
#define NG    4                      // m-slices per block
#define NT    (NN * NG)              // 768 threads
#define MS    (NN / NG)              // 48 m per slice
#define SROW  196                    // padded smem row stride (floats)
#define SGS_F (NN * SROW)            // 37632
#define XS_F  (8 * NN)               // staged vectors
#define PT_F  (8 * NG * NN)          // partials
#define HS_F  (NG * 192)
#define SMEM_BYTES ((SGS_F + XS_F + PT_F + HS_F) * 4)   // 184,320 B

#define FMA_X2(d, a, b, c) \
    asm("fma.rn.f32x2 %0, %1, %2, %3;" : "=l"(d) : "l"(a), "l"(b), "l"(c))

// ---- device-global scratch ----
__device__ float g_XG[196608];  // interleaved {x1, g1} per (pair, n)
__device__ float g_P1[49152];
__device__ float g_P2[49152];
__device__ float g_P3[49152];

// ---- replay-safe grid barrier ----
__device__ unsigned g_cnt = 0;
__device__ volatile unsigned g_gen = 0;

__device__ __forceinline__ void gsync() {
    __syncthreads();
    if (threadIdx.x == 0) {
        __threadfence();
        unsigned gen0 = g_gen;
        if (atomicAdd(&g_cnt, 1u) == GRID - 1) {
            g_cnt = 0;
            __threadfence();
            g_gen = gen0 + 1;
        } else {
            while (g_gen == gen0) { }
        }
        __threadfence();
    }
    __syncthreads();
}

// x0 accessor: 0 = raw X (N,T); 1 = buffer [(t*C+c)*NN+n]; 5 = up2+relu half-T
template <int X0M>
__device__ __forceinline__ float x0get(const float* __restrict__ P,
                                       int t, int c, int n, int C) {
    if (X0M == 0) return P[n * 32 + t];
    if (X0M == 1) return P[(t * C + c) * NN + n];
    if (t & 1) return 0.0f;
    float v = P[((t >> 1) * C + c) * NN + n];
    return v > 0.0f ? v : 0.0f;
}

// Partial matvec with packed f32x2 FMA: thread (n,g) accumulates
// Sg[n][slice g] against V staged vectors; partial -> part[(v*NG+g)*NN+n].
template <int V>
__device__ __forceinline__ void mvpart(const float* __restrict__ sgs,
                                       const float* __restrict__ xs,
                                       float* __restrict__ part, int n, int g) {
    unsigned long long a0[V], a1[V];
#pragma unroll
    for (int v = 0; v < V; v++) { a0[v] = 0ull; a1[v] = 0ull; }
    const ulonglong2* __restrict__ srow =
        (const ulonglong2*)(sgs + n * SROW + g * MS);
#pragma unroll
    for (int q = 0; q < MS / 4; q++) {
        const ulonglong2 s2 = srow[q];
#pragma unroll
        for (int v = 0; v < V; v++) {
            const ulonglong2 x2 =
                ((const ulonglong2*)(xs + v * NN + g * MS))[q];
            FMA_X2(a0[v], s2.x, x2.x, a0[v]);
            FMA_X2(a1[v], s2.y, x2.y, a1[v]);
        }
    }
#pragma unroll
    for (int v = 0; v < V; v++) {
        float2 f0 = *(float2*)&a0[v];
        float2 f1 = *(float2*)&a1[v];
        part[(v * NG + g) * NN + n] = (f0.x + f0.y) + (f1.x + f1.y);
    }
}

__device__ __forceinline__ float rsum(const float* __restrict__ part,
                                      int v, int n) {
    return (part[(v * NG + 0) * NN + n] + part[(v * NG + 1) * NN + n])
         + (part[(v * NG + 2) * NN + n] + part[(v * NG + 3) * NN + n]);
}

// ---------------------------------------------------------------------------
// Encoder AB (NP pairs/block): pass1 g0(t_j), g0(t_j-1); x1 = s.(x0,g0);
// pass2 g1 = Sg@x1. Writes {x1,g1} -> g_XG. Inactive blocks return early.
// ---------------------------------------------------------------------------
template <int NP, int X0M>
__device__ void ab_enc(const float* __restrict__ P, const float* __restrict__ sgs,
                       float* xs, float* part,
                       float s00, float s01, float s10, float s11,
                       int C, int T, int npairs, int n, int g, int b) {
    const int p0 = b * NP;
    if (p0 >= npairs) return;

#pragma unroll
    for (int v = g; v < 2 * NP; v += NG) {
        const int j = (v < NP) ? v : v - NP;
        const int pc = p0 + j;
        int t = pc / C;
        const int c = pc % C;
        if (v >= NP) t = (t + T - 1) % T;
        xs[v * NN + n] = x0get<X0M>(P, t, c, n, C);
    }
    __syncthreads();

    mvpart<2 * NP>(sgs, xs, part, n, g);
    __syncthreads();

    if (g < NP) {
        const int j = g;
        const float g0t = rsum(part, j, n);
        const float g0m = rsum(part, NP + j, n);
        const float x1 = s00 * xs[j * NN + n] + s01 * g0t
                       + s10 * xs[(NP + j) * NN + n] + s11 * g0m;
        xs[j * NN + n] = x1;
    }
    __syncthreads();

    mvpart<NP>(sgs, xs, part, n, g);
    __syncthreads();

    if (g < NP) {
        const int j = g;
        const float g1 = rsum(part, j, n);
        ((float2*)g_XG)[(p0 + j) * NN + n] = make_float2(xs[j * NN + n], g1);
    }
}

// ---------------------------------------------------------------------------
// Decoder AB (NP pairs/block): x0 = zero-stuff up2(+relu); g0 odd-t zero.
//   u = t>>1; t even: x1 = s00*x0u + s01*g0u ; t odd: x1 = s10*x0u + s11*g0u
// ---------------------------------------------------------------------------
template <int NP>
__device__ void ab_dec(const float* __restrict__ P, const float* __restrict__ sgs,
                       float* xs, float* part,
                       float s00, float s01, float s10, float s11,
                       int C, int n, int g, int b) {
    const int p0 = b * NP;

#pragma unroll
    for (int j = g; j < NP; j += NG) {
        const int pc = p0 + j;
        const int t = pc / C, c = pc % C, u = t >> 1;
        const float v = P[(u * C + c) * NN + n];
        xs[j * NN + n] = v > 0.0f ? v : 0.0f;
    }
    __syncthreads();

    mvpart<NP>(sgs, xs, part, n, g);
    __syncthreads();

    if (g < NP) {
        const int j = g;
        const int t = (p0 + j) / C;
        const float g0 = rsum(part, j, n);
        const float ca = (t & 1) ? s10 : s00;
        const float cb = (t & 1) ? s11 : s01;
        xs[j * NN + n] = ca * xs[j * NN + n] + cb * g0;
    }
    __syncthreads();

    mvpart<NP>(sgs, xs, part, n, g);
    __syncthreads();

    if (g < NP) {
        const int j = g;
        const float g1 = rsum(part, j, n);
        ((float2*)g_XG)[(p0 + j) * NN + n] = make_float2(xs[j * NN + n], g1);
    }
}

// ---------------------------------------------------------------------------
// Projection: y = sum_c x0*h0 + x1*h1 + x2*h2;
// x2 = s00*x1(t)+s01*g1(t)+s10*x1(tm)+s11*g1(tm). {x1,g1} float2 loads.
// EMODE 0: pool time pair + relu; 1: plain; 2: COUT==1 transpose write.
// ---------------------------------------------------------------------------
template <int CIN, int COUT, int OG, int EMODE, int X0M>
__device__ void proj(const float* __restrict__ P, const float* __restrict__ h,
                     float s00, float s01, float s10, float s11,
                     float* __restrict__ outp, int T, float* hsg, int n, int vb) {
    const int ogroups = COUT / OG;
    const int items = (EMODE == 0 ? T / 2 : T) * ogroups;
    const bool act = vb < items;
    const int it = act ? vb : items - 1;
    const int og = it % ogroups, ti = it / ogroups, o0 = og * OG;

    for (int idx = n; idx < OG * CIN * 3; idx += NN)
        hsg[idx] = h[o0 * CIN * 3 + idx];
    __syncthreads();

    const int nt = (EMODE == 0) ? 2 : 1;
    const int tb = (EMODE == 0) ? ti * 2 : ti;
    const float2* __restrict__ XG = (const float2*)g_XG;

    float best[OG];
#pragma unroll
    for (int o = 0; o < OG; o++) best[o] = -3.0e38f;

    for (int q = 0; q < nt; q++) {
        const int t = tb + q, tm = (t + T - 1) % T;
        float y[OG];
#pragma unroll
        for (int o = 0; o < OG; o++) y[o] = 0.0f;

#pragma unroll 8
        for (int c = 0; c < CIN; c++) {
            const float v0 = x0get<X0M>(P, t, c, n, CIN);
            const float2 xgt = XG[(t  * CIN + c) * NN + n];
            const float2 xgm = XG[(tm * CIN + c) * NN + n];
            const float v2 = s00 * xgt.x + s01 * xgt.y
                           + s10 * xgm.x + s11 * xgm.y;
#pragma unroll
            for (int o = 0; o < OG; o++) {
                const float* hp = &hsg[(o * CIN + c) * 3];
                y[o] = fmaf(v0,    hp[0], y[o]);
                y[o] = fmaf(xgt.x, hp[1], y[o]);
                y[o] = fmaf(v2,    hp[2], y[o]);
            }
        }

        if (EMODE == 0) {
#pragma unroll
            for (int o = 0; o < OG; o++) best[o] = fmaxf(best[o], y[o]);
        } else if (EMODE == 1) {
            if (act)
#pragma unroll
                for (int o = 0; o < OG; o++)
                    outp[(t * COUT + o0 + o) * NN + n] = y[o];
        } else {
            if (act) outp[n * T + t] = y[0];
        }
    }
    if (EMODE == 0 && act) {
#pragma unroll
        for (int o = 0; o < OG; o++)
            outp[(ti * COUT + o0 + o) * NN + n] = fmaxf(best[o], 0.0f);
    }
    __syncthreads();
}

// ---------------------------------------------------------------------------
// Single fused kernel: 768 thr = 192 n x 4 m-slices; smem-resident Sg.
// ---------------------------------------------------------------------------
extern __shared__ float sm[];
__global__ void __launch_bounds__(NT, 1)
fused(const float* __restrict__ X,  const float* __restrict__ Sg,
      const float* __restrict__ s4,
      const float* __restrict__ he1, const float* __restrict__ he2,
      const float* __restrict__ hd1, const float* __restrict__ hd2,
      float* __restrict__ out) {
    const int tid = threadIdx.x;
    const int g   = tid / NN;
    const int n   = tid % NN;
    const int b   = blockIdx.x;
    const int vb  = b * NG + g;

    float* sgs  = sm;
    float* xs   = sm + SGS_F;
    float* part = xs + XS_F;
    float* hsg  = part + PT_F + g * 192;

    {   // Fill Sg into padded smem, float4 coalesced.
        const float4* __restrict__ src = (const float4*)Sg;
#pragma unroll
        for (int i = tid; i < NN * (NN / 4); i += NT) {
            const int row = i / (NN / 4), qq = i % (NN / 4);
            ((float4*)(sgs + row * SROW))[qq] = src[row * (NN / 4) + qq];
        }
    }
    __syncthreads();

    const float s00 = s4[0], s01 = s4[1], s10 = s4[2], s11 = s4[3];

    // ---- Encoder layer 1: T=32, C=1 -> 16 (32 pairs, NP=1: blocks 0..31) ----
    ab_enc<1, 0>(X, sgs, xs, part, s00, s01, s10, s11, 1, 32, 32, n, g, b);
    gsync();
    proj<1, 16, 2, 0, 0>(X, he1, s00, s01, s10, s11, g_P1, 32, hsg, n, vb);
    gsync();

    // ---- Encoder layer 2: T=16, C=16 -> 32 (256 pairs, NP=2: all blocks) ----
    ab_enc<2, 1>(g_P1, sgs, xs, part, s00, s01, s10, s11, 16, 16, 256, n, g, b);
    gsync();
    proj<16, 32, 2, 0, 1>(g_P1, he2, s00, s01, s10, s11, g_P2, 16, hsg, n, vb);
    gsync();

    // ---- Decoder layer 1: up 8->16 (+relu), C=32 -> 16 (512 pairs, NP=4) ----
    ab_dec<4>(g_P2, sgs, xs, part, s00, s01, s10, s11, 32, n, g, b);
    gsync();
    proj<32, 16, 2, 1, 5>(g_P2, hd1, s00, s01, s10, s11, g_P3, 16, hsg, n, vb);
    gsync();

    // ---- Decoder layer 2: up 16->32 (+relu), C=16 -> 1 (512 pairs, NP=4) ----
    ab_dec<4>(g_P3, sgs, xs, part, s00, s01, s10, s11, 16, n, g, b);
    gsync();
    proj<16, 1, 1, 2, 5>(g_P3, hd2, s00, s01, s10, s11, out, 32, hsg, n, vb);
}

extern "C" void kernel_launch(void* const* d_in, const int* in_sizes, int n_in,
                              void* d_out, int out_size) {
    const float* X   = (const float*)d_in[0];  // (192, 32)
    const float* Sg  = (const float*)d_in[1];  // (192, 192)
    const float* s   = (const float*)d_in[2];  // (2, 2)
    const float* he1 = (const float*)d_in[3];  // (16, 1, 3)
    const float* he2 = (const float*)d_in[4];  // (32, 16, 3)
    const float* hd1 = (const float*)d_in[5];  // (16, 32, 3)
    const float* hd2 = (const float*)d_in[6];  // (1, 16, 3)
    float* out = (float*)d_out;                // (192, 32)

    cudaFuncSetAttribute(fused, cudaFuncAttributeMaxDynamicSharedMemorySize,
                         SMEM_BYTES);
    fused<<<GRID, NT, SMEM_BYTES>>>(X, Sg, s, he1, he2, hd1, hd2, out);
}

// round 8
// speedup vs baseline: 1.7946x; 1.1261x over previous
#include <cuda_runtime.h>

#define NN    192
#define GRID  128
#define NG    4                      // m-slices / work-split groups per block
#define NT    (NN * NG)              // 768 threads
#define MS    (NN / NG)              // 48 m per slice
#define SROW  196                    // padded smem row stride (floats)
#define SGS_F (NN * SROW)            // 37632
#define XS_F  (8 * NN)
#define PT_F  (32 * NN)              // partials (proj1 needs 32 slots)
#define HS_F  192
#define SMEM_BYTES ((SGS_F + XS_F + PT_F + HS_F) * 4)   // 182,016 B

#define FMA_X2(d, a, b, c) \
    asm("fma.rn.f32x2 %0, %1, %2, %3;" : "=l"(d) : "l"(a), "l"(b), "l"(c))

// ---- device-global scratch ----
__device__ float g_XG[196608];  // interleaved {x1, g1} per (pair, n)
__device__ float g_P1[49152];   // [(t*16+o)*NN+n]
__device__ float g_P2[49152];   // [(t*32+o)*NN+n]
__device__ float g_P3[49152];   // [(t*16+o)*NN+n]

// ---- replay-safe grid barrier ----
__device__ unsigned g_cnt = 0;
__device__ volatile unsigned g_gen = 0;

__device__ __forceinline__ void gsync() {
    __syncthreads();
    if (threadIdx.x == 0) {
        __threadfence();
        unsigned gen0 = g_gen;
        if (atomicAdd(&g_cnt, 1u) == GRID - 1) {
            g_cnt = 0;
            __threadfence();
            g_gen = gen0 + 1;
        } else {
            while (g_gen == gen0) { }
        }
        __threadfence();
    }
    __syncthreads();
}

// x0 accessor modes (see call sites)
template <int X0M>
__device__ __forceinline__ float x0get(const float* __restrict__ P,
                                       int t, int c, int n, int C) {
    if (X0M == 0) return P[n * 32 + t];
    if (X0M == 1) return P[(t * C + c) * NN + n];
    if (t & 1) return 0.0f;
    float v = P[((t >> 1) * C + c) * NN + n];
    return v > 0.0f ? v : 0.0f;
}

// Partial matvec (packed f32x2 FMA): thread (n,g) covers m-slice g.
template <int V>
__device__ __forceinline__ void mvpart(const float* __restrict__ sgs,
                                       const float* __restrict__ xs,
                                       float* __restrict__ part, int n, int g) {
    unsigned long long a0[V], a1[V];
#pragma unroll
    for (int v = 0; v < V; v++) { a0[v] = 0ull; a1[v] = 0ull; }
    const ulonglong2* __restrict__ srow =
        (const ulonglong2*)(sgs + n * SROW + g * MS);
#pragma unroll
    for (int q = 0; q < MS / 4; q++) {
        const ulonglong2 s2 = srow[q];
#pragma unroll
        for (int v = 0; v < V; v++) {
            const ulonglong2 x2 =
                ((const ulonglong2*)(xs + v * NN + g * MS))[q];
            FMA_X2(a0[v], s2.x, x2.x, a0[v]);
            FMA_X2(a1[v], s2.y, x2.y, a1[v]);
        }
    }
#pragma unroll
    for (int v = 0; v < V; v++) {
        float2 f0 = *(float2*)&a0[v];
        float2 f1 = *(float2*)&a1[v];
        part[(v * NG + g) * NN + n] = (f0.x + f0.y) + (f1.x + f1.y);
    }
}

__device__ __forceinline__ float rsum(const float* __restrict__ part,
                                      int v, int n) {
    return (part[(v * NG + 0) * NN + n] + part[(v * NG + 1) * NN + n])
         + (part[(v * NG + 2) * NN + n] + part[(v * NG + 3) * NN + n]);
}

// ---------------------------------------------------------------------------
// Encoder AB (NP pairs/block): g0(t), g0(t-1); x1 = s.(x0,g0); g1 = Sg@x1.
// ---------------------------------------------------------------------------
template <int NP, int X0M>
__device__ void ab_enc(const float* __restrict__ P, const float* __restrict__ sgs,
                       float* xs, float* part,
                       float s00, float s01, float s10, float s11,
                       int C, int T, int npairs, int n, int g, int b) {
    const int p0 = b * NP;
    if (p0 >= npairs) return;

#pragma unroll
    for (int v = g; v < 2 * NP; v += NG) {
        const int j = (v < NP) ? v : v - NP;
        const int pc = p0 + j;
        int t = pc / C;
        const int c = pc % C;
        if (v >= NP) t = (t + T - 1) % T;
        xs[v * NN + n] = x0get<X0M>(P, t, c, n, C);
    }
    __syncthreads();

    mvpart<2 * NP>(sgs, xs, part, n, g);
    __syncthreads();

    if (g < NP) {
        const int j = g;
        const float g0t = rsum(part, j, n);
        const float g0m = rsum(part, NP + j, n);
        const float x1 = s00 * xs[j * NN + n] + s01 * g0t
                       + s10 * xs[(NP + j) * NN + n] + s11 * g0m;
        xs[j * NN + n] = x1;
    }
    __syncthreads();

    mvpart<NP>(sgs, xs, part, n, g);
    __syncthreads();

    if (g < NP) {
        const int j = g;
        const float g1 = rsum(part, j, n);
        ((float2*)g_XG)[(p0 + j) * NN + n] = make_float2(xs[j * NN + n], g1);
    }
}

// ---------------------------------------------------------------------------
// Decoder AB (NP pairs/block): x0 = zero-stuff up2(+relu); g0 odd-t zero.
// ---------------------------------------------------------------------------
template <int NP>
__device__ void ab_dec(const float* __restrict__ P, const float* __restrict__ sgs,
                       float* xs, float* part,
                       float s00, float s01, float s10, float s11,
                       int C, int n, int g, int b) {
    const int p0 = b * NP;

#pragma unroll
    for (int j = g; j < NP; j += NG) {
        const int pc = p0 + j;
        const int t = pc / C, c = pc % C, u = t >> 1;
        const float v = P[(u * C + c) * NN + n];
        xs[j * NN + n] = v > 0.0f ? v : 0.0f;
    }
    __syncthreads();

    mvpart<NP>(sgs, xs, part, n, g);
    __syncthreads();

    if (g < NP) {
        const int j = g;
        const int t = (p0 + j) / C;
        const float g0 = rsum(part, j, n);
        const float ca = (t & 1) ? s10 : s00;
        const float cb = (t & 1) ? s11 : s01;
        xs[j * NN + n] = ca * xs[j * NN + n] + cb * g0;
    }
    __syncthreads();

    mvpart<NP>(sgs, xs, part, n, g);
    __syncthreads();

    if (g < NP) {
        const int j = g;
        const float g1 = rsum(part, j, n);
        ((float2*)g_XG)[(p0 + j) * NN + n] = make_float2(xs[j * NN + n], g1);
    }
}

// ---------------------------------------------------------------------------
// proj1 (enc1): CIN=1, COUT=16, T=32, pool+relu -> g_P1. 16 items (blocks 0-15).
// Groups 0,1 take t-parity; group 0 combines.
// ---------------------------------------------------------------------------
__device__ void proj1(const float* __restrict__ X, const float* __restrict__ h,
                      float s00, float s01, float s10, float s11,
                      float* part, float* hsg, int n, int g, int b) {
    if (b >= 16) return;
    if (threadIdx.x < 48) hsg[threadIdx.x] = h[threadIdx.x];
    __syncthreads();

    const int ti = b;
    const float2* __restrict__ XG = (const float2*)g_XG;
    if (g < 2) {
        const int t = ti * 2 + g, tm = (t + 31) & 31;
        const float v0 = X[n * 32 + t];
        const float2 xgt = XG[t * NN + n];
        const float2 xgm = XG[tm * NN + n];
        const float v2 = s00 * xgt.x + s01 * xgt.y + s10 * xgm.x + s11 * xgm.y;
#pragma unroll
        for (int o = 0; o < 16; o++) {
            float y = v0 * hsg[o * 3] + xgt.x * hsg[o * 3 + 1]
                    + v2 * hsg[o * 3 + 2];
            part[(g * 16 + o) * NN + n] = y;
        }
    }
    __syncthreads();
    if (g == 0) {
#pragma unroll
        for (int o = 0; o < 16; o++) {
            float y = fmaxf(part[o * NN + n], part[(16 + o) * NN + n]);
            g_P1[(ti * 16 + o) * NN + n] = fmaxf(y, 0.0f);
        }
    }
    __syncthreads();
}

// ---------------------------------------------------------------------------
// proj2 (enc2): CIN=16, COUT=32, T=16, pool+relu -> g_P2.
// 128 items = (ti in 0..7) x (og in 0..15), OG=2. Groups = (t-parity, c-half).
// ---------------------------------------------------------------------------
__device__ void proj2(const float* __restrict__ h,
                      float s00, float s01, float s10, float s11,
                      float* part, float* hsg, int n, int g, int b) {
    const int og = b & 15, ti = b >> 4, o0 = og * 2;
    if (threadIdx.x < 96) hsg[threadIdx.x] = h[o0 * 48 + threadIdx.x];
    __syncthreads();

    const int q = g >> 1, ch = g & 1;
    const int t = ti * 2 + q, tm = (t + 15) & 15;
    const float2* __restrict__ XG = (const float2*)g_XG;
    float y0 = 0.0f, y1 = 0.0f;
#pragma unroll
    for (int cc = 0; cc < 8; cc++) {
        const int c = ch * 8 + cc;
        const float v0 = g_P1[(t * 16 + c) * NN + n];
        const float2 xgt = XG[(t * 16 + c) * NN + n];
        const float2 xgm = XG[(tm * 16 + c) * NN + n];
        const float v2 = s00 * xgt.x + s01 * xgt.y + s10 * xgm.x + s11 * xgm.y;
        const float* hp0 = &hsg[c * 3];
        const float* hp1 = &hsg[48 + c * 3];
        y0 = fmaf(v0, hp0[0], y0); y0 = fmaf(xgt.x, hp0[1], y0);
        y0 = fmaf(v2, hp0[2], y0);
        y1 = fmaf(v0, hp1[0], y1); y1 = fmaf(xgt.x, hp1[1], y1);
        y1 = fmaf(v2, hp1[2], y1);
    }
    part[(g * 2 + 0) * NN + n] = y0;
    part[(g * 2 + 1) * NN + n] = y1;
    __syncthreads();
    if (g == 0) {
#pragma unroll
        for (int o = 0; o < 2; o++) {
            const float ya = part[(0 * 2 + o) * NN + n] + part[(1 * 2 + o) * NN + n];
            const float yb = part[(2 * 2 + o) * NN + n] + part[(3 * 2 + o) * NN + n];
            g_P2[(ti * 32 + o0 + o) * NN + n] = fmaxf(fmaxf(ya, yb), 0.0f);
        }
    }
    __syncthreads();
}

// ---------------------------------------------------------------------------
// proj3 (dec1): CIN=32, COUT=16, T=16, plain -> g_P3. x0 = up2+relu of g_P2.
// 128 items = (t in 0..15) x (og in 0..7), OG=2. Groups split c into quarters.
// ---------------------------------------------------------------------------
__device__ void proj3(const float* __restrict__ h,
                      float s00, float s01, float s10, float s11,
                      float* part, float* hsg, int n, int g, int b) {
    const int og = b & 7, t = b >> 3, o0 = og * 2;
    for (int i = threadIdx.x; i < 192; i += NT) hsg[i] = h[o0 * 96 + i];
    __syncthreads();

    const int tm = (t + 15) & 15;
    const float2* __restrict__ XG = (const float2*)g_XG;
    float y0 = 0.0f, y1 = 0.0f;
#pragma unroll
    for (int cc = 0; cc < 8; cc++) {
        const int c = g * 8 + cc;
        const float v0 = x0get<5>(g_P2, t, c, n, 32);
        const float2 xgt = XG[(t * 32 + c) * NN + n];
        const float2 xgm = XG[(tm * 32 + c) * NN + n];
        const float v2 = s00 * xgt.x + s01 * xgt.y + s10 * xgm.x + s11 * xgm.y;
        const float* hp0 = &hsg[c * 3];
        const float* hp1 = &hsg[96 + c * 3];
        y0 = fmaf(v0, hp0[0], y0); y0 = fmaf(xgt.x, hp0[1], y0);
        y0 = fmaf(v2, hp0[2], y0);
        y1 = fmaf(v0, hp1[0], y1); y1 = fmaf(xgt.x, hp1[1], y1);
        y1 = fmaf(v2, hp1[2], y1);
    }
    part[(g * 2 + 0) * NN + n] = y0;
    part[(g * 2 + 1) * NN + n] = y1;
    __syncthreads();
    if (g == 0) {
#pragma unroll
        for (int o = 0; o < 2; o++) {
            float y = (part[(0 * 2 + o) * NN + n] + part[(1 * 2 + o) * NN + n])
                    + (part[(2 * 2 + o) * NN + n] + part[(3 * 2 + o) * NN + n]);
            g_P3[(t * 16 + o0 + o) * NN + n] = y;
        }
    }
    __syncthreads();
}

// ---------------------------------------------------------------------------
// proj4 (dec2): CIN=16, COUT=1, T=32, transpose -> out. x0 = up2+relu of g_P3.
// 32 items (blocks 0-31). Groups split c into quarters (4 each).
// ---------------------------------------------------------------------------
__device__ void proj4(const float* __restrict__ h, float* __restrict__ outp,
                      float s00, float s01, float s10, float s11,
                      float* part, float* hsg, int n, int g, int b) {
    if (b >= 32) return;
    if (threadIdx.x < 48) hsg[threadIdx.x] = h[threadIdx.x];
    __syncthreads();

    const int t = b, tm = (t + 31) & 31;
    const float2* __restrict__ XG = (const float2*)g_XG;
    float y = 0.0f;
#pragma unroll
    for (int cc = 0; cc < 4; cc++) {
        const int c = g * 4 + cc;
        const float v0 = x0get<5>(g_P3, t, c, n, 16);
        const float2 xgt = XG[(t * 16 + c) * NN + n];
        const float2 xgm = XG[(tm * 16 + c) * NN + n];
        const float v2 = s00 * xgt.x + s01 * xgt.y + s10 * xgm.x + s11 * xgm.y;
        const float* hp = &hsg[c * 3];
        y = fmaf(v0, hp[0], y); y = fmaf(xgt.x, hp[1], y);
        y = fmaf(v2, hp[2], y);
    }
    part[g * NN + n] = y;
    __syncthreads();
    if (g == 0) {
        outp[n * 32 + t] = (part[n] + part[NN + n])
                         + (part[2 * NN + n] + part[3 * NN + n]);
    }
    __syncthreads();
}

// ---------------------------------------------------------------------------
// Single fused kernel.
// ---------------------------------------------------------------------------
extern __shared__ float sm[];
__global__ void __launch_bounds__(NT, 1)
fused(const float* __restrict__ X,  const float* __restrict__ Sg,
      const float* __restrict__ s4,
      const float* __restrict__ he1, const float* __restrict__ he2,
      const float* __restrict__ hd1, const float* __restrict__ hd2,
      float* __restrict__ out) {
    const int tid = threadIdx.x;
    const int g   = tid / NN;
    const int n   = tid % NN;
    const int b   = blockIdx.x;

    float* sgs  = sm;
    float* xs   = sm + SGS_F;
    float* part = xs + XS_F;
    float* hsg  = part + PT_F;

    {   // Fill Sg into padded smem, float4 coalesced.
        const float4* __restrict__ src = (const float4*)Sg;
#pragma unroll
        for (int i = tid; i < NN * (NN / 4); i += NT) {
            const int row = i / (NN / 4), qq = i % (NN / 4);
            ((float4*)(sgs + row * SROW))[qq] = src[row * (NN / 4) + qq];
        }
    }
    __syncthreads();

    const float s00 = s4[0], s01 = s4[1], s10 = s4[2], s11 = s4[3];

    // ---- Encoder layer 1 ----
    ab_enc<1, 0>(X, sgs, xs, part, s00, s01, s10, s11, 1, 32, 32, n, g, b);
    gsync();
    proj1(X, he1, s00, s01, s10, s11, part, hsg, n, g, b);
    gsync();

    // ---- Encoder layer 2 ----
    ab_enc<2, 1>(g_P1, sgs, xs, part, s00, s01, s10, s11, 16, 16, 256, n, g, b);
    gsync();
    proj2(he2, s00, s01, s10, s11, part, hsg, n, g, b);
    gsync();

    // ---- Decoder layer 1 ----
    ab_dec<4>(g_P2, sgs, xs, part, s00, s01, s10, s11, 32, n, g, b);
    gsync();
    proj3(hd1, s00, s01, s10, s11, part, hsg, n, g, b);
    gsync();

    // ---- Decoder layer 2 ----
    ab_dec<4>(g_P3, sgs, xs, part, s00, s01, s10, s11, 16, n, g, b);
    gsync();
    proj4(hd2, out, s00, s01, s10, s11, part, hsg, n, g, b);
}

extern "C" void kernel_launch(void* const* d_in, const int* in_sizes, int n_in,
                              void* d_out, int out_size) {
    const float* X   = (const float*)d_in[0];  // (192, 32)
    const float* Sg  = (const float*)d_in[1];  // (192, 192)
    const float* s   = (const float*)d_in[2];  // (2, 2)
    const float* he1 = (const float*)d_in[3];  // (16, 1, 3)
    const float* he2 = (const float*)d_in[4];  // (32, 16, 3)
    const float* hd1 = (const float*)d_in[5];  // (16, 32, 3)
    const float* hd2 = (const float*)d_in[6];  // (1, 16, 3)
    float* out = (float*)d_out;                // (192, 32)

    cudaFuncSetAttribute(fused, cudaFuncAttributeMaxDynamicSharedMemorySize,
                         SMEM_BYTES);
    fused<<<GRID, NT, SMEM_BYTES>>>(X, Sg, s, he1, he2, hd1, hd2, out);
}